// round 8
// baseline (speedup 1.0000x reference)
#include <cuda_runtime.h>

#define NN 16000
#define KNN 16
#define FIN 32
#define HID 64
#define G 64
#define NCELL (G * G)
#define CAP 32            // max points per cell (lambda ~3.9)
#define TILE 4
#define MARG 2
#define WIN 8             // TILE + 2*MARG
#define WCELLS (WIN * WIN)
#define SPTS_CAP 1024     // staged-point capacity (expected ~250)
#define NTB (G / TILE)    // 16 tiles per axis

// ---------------- scratch (device globals; no allocation allowed) ----------
__device__ float4 g_pts[NN];              // {x, y, x^2+y^2, id-bits}
__device__ float4 g_binpts[NCELL * CAP];  // packed candidates per cell
__device__ int    g_bcnt[NCELL];          // per-cell fill counts
__device__ int    g_knn[NN * KNN];        // neighbor (src) indices (sorted)
__device__ float  g_d  [NN * KNN];        // edge distances
__device__ float  g_ew [NN * KNN];        // normalized inverted distances
__device__ float  g_dis[NN];              // deg^{-1/2}
__device__ unsigned g_minmax[2];          // [0]=min bits, [1]=max bits (d>=0)
__device__ unsigned g_bbox[4];            // ordered-uint minx,maxx,miny,maxy
__device__ float  g_bufA[NN * HID];       // x@W1
__device__ float  g_bufB[NN * HID];       // h1@W2

// ordered-uint map: monotone with float order (handles negatives)
__device__ __forceinline__ unsigned enc_ord(float f) {
    unsigned b = __float_as_uint(f);
    return (b & 0x80000000u) ? ~b : (b | 0x80000000u);
}
__device__ __forceinline__ float dec_ord(unsigned u) {
    return (u & 0x80000000u) ? __uint_as_float(u & 0x7FFFFFFFu)
                             : __uint_as_float(~u);
}

struct Grid { float minx, miny, invsx, invsy, smin; };
__device__ __forceinline__ Grid load_grid() {
    Grid g;
    g.minx = dec_ord(g_bbox[0]);
    float maxx = dec_ord(g_bbox[1]);
    g.miny = dec_ord(g_bbox[2]);
    float maxy = dec_ord(g_bbox[3]);
    float wx = fmaxf(maxx - g.minx, 1e-20f);
    float wy = fmaxf(maxy - g.miny, 1e-20f);
    g.invsx = (float)G / wx;
    g.invsy = (float)G / wy;
    g.smin  = fminf(wx, wy) / (float)G;
    return g;
}
__device__ __forceinline__ int cell_x(const Grid& g, float x) {
    int c = (int)((x - g.minx) * g.invsx);
    return min(max(c, 0), G - 1);
}
__device__ __forceinline__ int cell_y(const Grid& g, float y) {
    int c = (int)((y - g.miny) * g.invsy);
    return min(max(c, 0), G - 1);
}

// candidate processing: bit-exact d2 + min-16 of key=(ordered(d2)<<32|j)
// via branchless replace-max over distinct sentinels.
#define PROCESS(PT) do {                                                   \
    int j = __float_as_int((PT).w);                                        \
    float dot = __fmaf_rn(me.y, (PT).y, __fmul_rn(me.x, (PT).x));          \
    float d2  = __fsub_rn(__fadd_rn(me.z, (PT).z), __fmul_rn(2.0f, dot));  \
    unsigned long long key =                                               \
        ((unsigned long long)enc_ord(d2) << 32) | (unsigned)j;             \
    if (j != q && key < cmax) {                                            \
        unsigned long long nm = 0ULL;                                      \
        _Pragma("unroll")                                                  \
        for (int kk = 0; kk < 16; kk++) {                                  \
            if (keys[kk] == cmax) keys[kk] = key;                          \
            nm = max(nm, keys[kk]);                                        \
        }                                                                  \
        cmax = nm;                                                         \
    }                                                                      \
} while (0)

// ---------------- K1: init + pack + bbox (block-reduced atomics) ------------
__global__ void prep_kernel(const float* __restrict__ c) {
    __shared__ unsigned red[4][8];        // [stat][warp]
    int i = blockIdx.x * 256 + threadIdx.x;
    if (i < NCELL) g_bcnt[i] = 0;
    if (i == 0) { g_minmax[0] = 0x7F800000u; g_minmax[1] = 0u;
                  g_bbox[0] = 0xFFFFFFFFu; g_bbox[1] = 0u;
                  g_bbox[2] = 0xFFFFFFFFu; g_bbox[3] = 0u; }
    unsigned exn = 0xFFFFFFFFu, exx = 0u, eyn = 0xFFFFFFFFu, eyx = 0u;
    if (i < NN) {
        float x = c[2 * i], y = c[2 * i + 1];
        float sq = __fadd_rn(__fmul_rn(x, x), __fmul_rn(y, y));
        g_pts[i] = make_float4(x, y, sq, __int_as_float(i));
        unsigned ex = enc_ord(x), ey = enc_ord(y);
        exn = ex; exx = ex; eyn = ey; eyx = ey;
    }
    exn = __reduce_min_sync(0xFFFFFFFFu, exn);
    exx = __reduce_max_sync(0xFFFFFFFFu, exx);
    eyn = __reduce_min_sync(0xFFFFFFFFu, eyn);
    eyx = __reduce_max_sync(0xFFFFFFFFu, eyx);
    int w = threadIdx.x >> 5;
    if ((threadIdx.x & 31) == 0) {
        red[0][w] = exn; red[1][w] = exx; red[2][w] = eyn; red[3][w] = eyx;
    }
    __syncthreads();
    if (threadIdx.x < 4) {
        unsigned v = red[threadIdx.x][0];
        bool ismin = (threadIdx.x & 1) == 0;
#pragma unroll
        for (int k = 1; k < 8; k++)
            v = ismin ? min(v, red[threadIdx.x][k]) : max(v, red[threadIdx.x][k]);
        if (ismin) atomicMin(&g_bbox[threadIdx.x], v);
        else       atomicMax(&g_bbox[threadIdx.x], v);
    }
}

// ---------------- K2: bin fill -----------------------------------------------
__global__ void fill_kernel() {
    int i = blockIdx.x * 256 + threadIdx.x;
    if (i >= NN) return;
    Grid g = load_grid();
    float4 p = g_pts[i];
    int cell = cell_y(g, p.y) * G + cell_x(g, p.x);
    int slot = atomicAdd(&g_bcnt[cell], 1);
    if (slot < CAP) g_binpts[cell * CAP + slot] = p;
}

// ---------------- K3: x@W1 ---------------------------------------------------
__global__ void mm1_kernel(const float* __restrict__ x,
                           const float* __restrict__ W1) {
    __shared__ float sw[FIN * 64];
    int tid = threadIdx.x;
    for (int i = tid; i < FIN * 64; i += 256) sw[i] = W1[i];
    __syncthreads();
    int n = blockIdx.x * 4 + (tid >> 6);
    int f = tid & 63;
    const float* xr = x + n * FIN;
    float acc = 0.0f;
#pragma unroll
    for (int k = 0; k < FIN; k++) acc = fmaf(xr[k], sw[k * 64 + f], acc);
    g_bufA[n * 64 + f] = acc;
}

// ---------------- K4 (PROFILED): tile-staged exact KNN + edge distances -----
// Block = 4x4-cell tile; stages its 8x8 window (tile + 2-margin) into shared
// via prefix scan + compact copy. Queries = tile points, enumerated compactly
// over 64 threads. Rings r<=2 always lie inside the window (LDS reads);
// r>=3 (rare) and staging-overflow fall back to the identical global walk.
// Ring sets are Chebyshev-disjoint -> candidate set bit-identical to R7.
__global__ void knn_edge_kernel() {
    __shared__ float4 spts[SPTS_CAP];
    __shared__ int scanarr[WCELLS];
    __shared__ int pref[WCELLS + 1];
    __shared__ int tqoff[17];
    __shared__ unsigned smn, smx;

    const int tid = threadIdx.x;      // 64 threads
    if (tid == 0) { smn = 0x7F800000u; smx = 0u; }

    const int bx0 = (blockIdx.x & (NTB - 1)) * TILE;
    const int by0 = (blockIdx.x / NTB) * TILE;

    // window cell counts
    {
        int wx = tid & 7, wy = tid >> 3;
        int gx = bx0 + wx - MARG, gy = by0 + wy - MARG;
        int cnt = 0;
        if (gx >= 0 && gx < G && gy >= 0 && gy < G)
            cnt = min(g_bcnt[gy * G + gx], CAP);
        scanarr[tid] = cnt;
    }
    __syncthreads();
    for (int off = 1; off < WCELLS; off <<= 1) {
        int v = (tid >= off) ? scanarr[tid - off] : 0;
        __syncthreads();
        scanarr[tid] += v;
        __syncthreads();
    }
    pref[tid + 1] = scanarr[tid];
    if (tid == 0) pref[0] = 0;
    __syncthreads();

    const int total = pref[WCELLS];
    const bool staged = (total <= SPTS_CAP);

    if (staged) {
        for (int i = tid; i < total; i += 64) {
            int lo = 0, hi = WCELLS - 1;
            while (lo < hi) {
                int mid = (lo + hi) >> 1;
                if (pref[mid + 1] <= i) lo = mid + 1; else hi = mid;
            }
            int w = lo, slot = i - pref[w];
            int gx = bx0 + (w & 7) - MARG, gy = by0 + (w >> 3) - MARG;
            spts[i] = g_binpts[(gy * G + gx) * CAP + slot];
        }
    }
    if (tid == 0) {
        int s = 0;
        for (int t = 0; t < 16; t++) {
            int w = (MARG + (t >> 2)) * WIN + MARG + (t & 3);
            tqoff[t] = s;
            s += pref[w + 1] - pref[w];
        }
        tqoff[16] = s;
    }
    __syncthreads();

    const int qtot = tqoff[16];
    const Grid g = load_grid();
    unsigned lmn = 0x7F800000u, lmx = 0u;

    for (int qi = tid; qi < qtot; qi += 64) {
        int tc = 0;
        while (tqoff[tc + 1] <= qi) tc++;
        const int w  = (MARG + (tc >> 2)) * WIN + (MARG + (tc & 3));
        const int lx = w & 7, ly = w >> 3;
        const int cx = bx0 + lx - MARG, cy = by0 + ly - MARG;
        const int off = qi - tqoff[tc];
        float4 me = staged ? spts[pref[w] + off]
                           : g_binpts[(cy * G + cx) * CAP + off];
        const int q = __float_as_int(me.w);

        unsigned long long keys[16];
#pragma unroll
        for (int k = 0; k < 16; k++) keys[k] = ~0ULL - (unsigned long long)k;
        unsigned long long cmax = ~0ULL;

        bool pruned = false;
        for (int r = 0; r <= 2; r++) {
            if (r == 2) {
                float b = g.smin;                       // (r-1)*smin, r=2
                float thr = dec_ord((unsigned)(cmax >> 32));
                if (b * b > thr + 1e-4f) { pruned = true; break; }
            }
            int y0 = ly - r, y1 = ly + r, x0 = lx - r, x1 = lx + r;
            for (int yy = y0; yy <= y1; yy++) {
                bool erow = (yy == y0) || (yy == y1);
                int xstep = (erow || r == 0) ? 1 : 2 * r;
                for (int xx = x0; xx <= x1; xx += xstep) {
                    if (staged) {
                        int w2 = yy * WIN + xx;
                        int p1 = pref[w2 + 1];
                        for (int p = pref[w2]; p < p1; p++) {
                            float4 pt = spts[p];
                            PROCESS(pt);
                        }
                    } else {
                        int gx2 = bx0 + xx - MARG, gy2 = by0 + yy - MARG;
                        if (gx2 < 0 || gx2 >= G || gy2 < 0 || gy2 >= G)
                            continue;
                        int cc = gy2 * G + gx2;
                        int cnt = min(g_bcnt[cc], CAP);
                        const float4* bp = &g_binpts[cc * CAP];
                        for (int p = 0; p < cnt; p++) {
                            float4 pt = bp[p];
                            PROCESS(pt);
                        }
                    }
                }
            }
        }
        if (!pruned) {
            for (int r = 3; r < G; r++) {
                float b = (float)(r - 1) * g.smin;
                float thr = dec_ord((unsigned)(cmax >> 32));
                if (b * b > thr + 1e-4f) break;
                int y0 = cy - r, y1 = cy + r, x0 = cx - r, x1 = cx + r;
                for (int yy = max(y0, 0); yy <= min(y1, G - 1); yy++) {
                    bool erow = (yy == y0) || (yy == y1);
                    int xstep = erow ? 1 : 2 * r;
                    for (int xx = x0; xx <= x1; xx += xstep) {
                        if (xx < 0 || xx >= G) continue;
                        int cc = yy * G + xx;
                        int cnt = min(g_bcnt[cc], CAP);
                        const float4* bp = &g_binpts[cc * CAP];
                        for (int p = 0; p < cnt; p++) {
                            float4 pt = bp[p];
                            PROCESS(pt);
                        }
                    }
                }
            }
        }

        // sort 16 keys ascending (static bubble network, registers only)
#pragma unroll
        for (int i = 0; i < 15; i++)
#pragma unroll
            for (int t = 0; t < 15 - i; t++)
                if (keys[t] > keys[t + 1]) {
                    unsigned long long tmp = keys[t];
                    keys[t] = keys[t + 1];
                    keys[t + 1] = tmp;
                }

        // edge epilogue: distances + local minmax
#pragma unroll
        for (int t = 0; t < 16; t++) {
            int j = (int)(keys[t] & 0xFFFFFFFFULL);
            g_knn[q * KNN + t] = j;
            float4 nb = g_pts[j];
            float dx = __fsub_rn(me.x, nb.x);
            float dy = __fsub_rn(me.y, nb.y);
            float d  = __fsqrt_rn(__fadd_rn(__fmul_rn(dx, dx),
                                            __fmul_rn(dy, dy)));
            g_d[q * KNN + t] = d;
            unsigned b = __float_as_uint(d);    // d>=0 -> order-preserving
            lmn = min(lmn, b);
            lmx = max(lmx, b);
        }
    }
    atomicMin(&smn, lmn);
    atomicMax(&smx, lmx);
    __syncthreads();
    if (tid == 0) {
        atomicMin(&g_minmax[0], smn);
        atomicMax(&g_minmax[1], smx);
    }
}

// ---------------- K5: edge weights + deg^{-1/2} (1 thread / edge) -----------
__global__ void deg_kernel() {
    int e = blockIdx.x * 256 + threadIdx.x;     // coalesced over edges
    float mx  = __uint_as_float(g_minmax[1]);
    float rng = __fsub_rn(mx, __uint_as_float(g_minmax[0]));
    float ew  = __fdiv_rn(__fsub_rn(mx, g_d[e]), rng);
    g_ew[e] = ew;
    float s = ew;
#pragma unroll
    for (int off = 8; off > 0; off >>= 1)
        s += __shfl_down_sync(0xFFFFFFFFu, s, off, 16);
    if ((threadIdx.x & 15) == 0)
        g_dis[e >> 4] = rsqrtf(__fadd_rn(1.0f, s));   // +1 self-loop
}

// ---------------- K6: agg1 + relu + h1@W2 (row-fused) -----------------------
#define NPB 8
__global__ void agg_mm2_kernel(const float* __restrict__ b1,
                               const float* __restrict__ W2) {
    __shared__ float sw[HID * 64];
    __shared__ float sh1[NPB][64];
    int tid = threadIdx.y * 64 + threadIdx.x;
    for (int i = tid; i < HID * 64; i += 64 * NPB) sw[i] = W2[i];
    int n = blockIdx.x * NPB + threadIdx.y;
    int f = threadIdx.x;
    float disn = g_dis[n];
    float acc = __fmul_rn(__fmul_rn(disn, disn), g_bufA[n * 64 + f]);
#pragma unroll
    for (int k = 0; k < KNN; k++) {
        int s = g_knn[n * KNN + k];
        float coef = __fmul_rn(__fmul_rn(g_dis[s], g_ew[n * KNN + k]), disn);
        acc = fmaf(coef, g_bufA[s * 64 + f], acc);
    }
    sh1[threadIdx.y][f] = fmaxf(__fadd_rn(acc, b1[f]), 0.0f);
    __syncthreads();
    float acc2 = 0.0f;
#pragma unroll
    for (int k = 0; k < HID; k++)
        acc2 = fmaf(sh1[threadIdx.y][k], sw[k * 64 + f], acc2);
    g_bufB[n * 64 + f] = acc2;
}

// ---------------- K7: agg2 + relu + FC head ---------------------------------
__global__ void final_kernel(const float* __restrict__ b2,
                             const float* __restrict__ wfc,
                             const float* __restrict__ bfc,
                             float* __restrict__ y) {
    __shared__ float red[NPB][64];
    int n = blockIdx.x * NPB + threadIdx.y;
    int f = threadIdx.x;
    float disn = g_dis[n];
    float acc = __fmul_rn(__fmul_rn(disn, disn), g_bufB[n * 64 + f]);
#pragma unroll
    for (int k = 0; k < KNN; k++) {
        int s = g_knn[n * KNN + k];
        float coef = __fmul_rn(__fmul_rn(g_dis[s], g_ew[n * KNN + k]), disn);
        acc = fmaf(coef, g_bufB[s * 64 + f], acc);
    }
    float h2 = fmaxf(__fadd_rn(acc, b2[f]), 0.0f);
    red[threadIdx.y][f] = h2 * wfc[f];
    __syncthreads();
#pragma unroll
    for (int off = 32; off > 0; off >>= 1) {
        if (f < off) red[threadIdx.y][f] += red[threadIdx.y][f + off];
        __syncthreads();
    }
    if (f == 0) y[n] = red[threadIdx.y][0] + bfc[0];
}

// ---------------- launch -----------------------------------------------------
extern "C" void kernel_launch(void* const* d_in, const int* in_sizes, int n_in,
                              void* d_out, int out_size) {
    const float* x   = (const float*)d_in[0];
    const float* c   = (const float*)d_in[1];
    const float* W1  = (const float*)d_in[2];
    const float* b1  = (const float*)d_in[3];
    const float* W2  = (const float*)d_in[4];
    const float* b2  = (const float*)d_in[5];
    const float* Wfc = (const float*)d_in[6];
    const float* bfc = (const float*)d_in[7];
    float* y = (float*)d_out;

    prep_kernel<<<63, 256>>>(c);            // launch 0
    fill_kernel<<<63, 256>>>();             // launch 1
    mm1_kernel<<<NN / 4, 256>>>(x, W1);     // launch 2
    knn_edge_kernel<<<NTB * NTB, 64>>>();   // launch 3  <- profiled slot
    deg_kernel<<<NN * KNN / 256, 256>>>();
    dim3 blk(64, NPB);
    agg_mm2_kernel<<<NN / NPB, blk>>>(b1, W2);
    final_kernel<<<NN / NPB, blk>>>(b2, Wfc, bfc, y);
}

// round 9
// speedup vs baseline: 1.1882x; 1.1882x over previous
#include <cuda_runtime.h>

#define NN 16000
#define KNN 16
#define FIN 32
#define HID 64
#define G 64
#define NCELL (G * G)
#define CAP 32            // max points per cell (lambda ~3.9)
#define QPB 8             // queries (=warps) per block
#define FULLM 0xFFFFFFFFu

// ---------------- scratch (device globals; no allocation allowed) ----------
__device__ float4 g_pts[NN];              // {x, y, x^2+y^2, id-bits}
__device__ float4 g_binpts[NCELL * CAP];  // packed candidates per cell
__device__ int    g_bcnt[NCELL];          // per-cell fill counts
__device__ int    g_knn[NN * KNN];        // neighbor (src) indices (sorted)
__device__ float  g_d  [NN * KNN];        // edge distances
__device__ float  g_ew [NN * KNN];        // normalized inverted distances
__device__ float  g_dis[NN];              // deg^{-1/2}
__device__ unsigned g_minmax[2];          // [0]=min bits, [1]=max bits (d>=0)
__device__ unsigned g_bbox[4];            // ordered-uint minx,maxx,miny,maxy
__device__ float  g_bufA[NN * HID];       // x@W1
__device__ float  g_bufB[NN * HID];       // h1@W2

// 5x5 window offsets in center-out ring order (tightens cmax early)
__constant__ signed char WDX[25] = {0, -1,0,1,-1,1,-1,0,1,
                                    -2,-1,0,1,2, -2,2, -2,2, -2,2, -2,-1,0,1,2};
__constant__ signed char WDY[25] = {0, -1,-1,-1,0,0,1,1,1,
                                    -2,-2,-2,-2,-2, -1,-1, 0,0, 1,1, 2,2,2,2,2};

// ordered-uint map: monotone with float order (handles negatives)
__device__ __forceinline__ unsigned enc_ord(float f) {
    unsigned b = __float_as_uint(f);
    return (b & 0x80000000u) ? ~b : (b | 0x80000000u);
}
__device__ __forceinline__ float dec_ord(unsigned u) {
    return (u & 0x80000000u) ? __uint_as_float(u & 0x7FFFFFFFu)
                             : __uint_as_float(~u);
}

struct Grid { float minx, miny, invsx, invsy, smin; };
__device__ __forceinline__ Grid load_grid() {
    Grid g;
    g.minx = dec_ord(g_bbox[0]);
    float maxx = dec_ord(g_bbox[1]);
    g.miny = dec_ord(g_bbox[2]);
    float maxy = dec_ord(g_bbox[3]);
    float wx = fmaxf(maxx - g.minx, 1e-20f);
    float wy = fmaxf(maxy - g.miny, 1e-20f);
    g.invsx = (float)G / wx;
    g.invsy = (float)G / wy;
    g.smin  = fminf(wx, wy) / (float)G;
    return g;
}
__device__ __forceinline__ int cell_x(const Grid& g, float x) {
    int c = (int)((x - g.minx) * g.invsx);
    return min(max(c, 0), G - 1);
}
__device__ __forceinline__ int cell_y(const Grid& g, float y) {
    int c = (int)((y - g.miny) * g.invsy);
    return min(max(c, 0), G - 1);
}

// bit-exact d2 + scalar replace-max into KEYS/CMAX (fallback path only)
#define PROCESS(PT, KEYS, CMAX) do {                                       \
    int j = __float_as_int((PT).w);                                        \
    float dot = __fmaf_rn(me.y, (PT).y, __fmul_rn(me.x, (PT).x));          \
    float d2  = __fsub_rn(__fadd_rn(me.z, (PT).z), __fmul_rn(2.0f, dot));  \
    unsigned long long key =                                               \
        ((unsigned long long)enc_ord(d2) << 32) | (unsigned)j;             \
    if (j != q && key < (CMAX)) {                                          \
        unsigned long long nm = 0ULL;                                      \
        _Pragma("unroll")                                                  \
        for (int kk = 0; kk < 16; kk++) {                                  \
            if ((KEYS)[kk] == (CMAX)) (KEYS)[kk] = key;                    \
            nm = max(nm, (KEYS)[kk]);                                      \
        }                                                                  \
        (CMAX) = nm;                                                       \
    }                                                                      \
} while (0)

// ---------------- K1: init + pack + bbox (block-reduced atomics) ------------
__global__ void prep_kernel(const float* __restrict__ c) {
    __shared__ unsigned red[4][8];
    int i = blockIdx.x * 256 + threadIdx.x;
    if (i < NCELL) g_bcnt[i] = 0;
    if (i == 0) { g_minmax[0] = 0x7F800000u; g_minmax[1] = 0u;
                  g_bbox[0] = 0xFFFFFFFFu; g_bbox[1] = 0u;
                  g_bbox[2] = 0xFFFFFFFFu; g_bbox[3] = 0u; }
    unsigned exn = 0xFFFFFFFFu, exx = 0u, eyn = 0xFFFFFFFFu, eyx = 0u;
    if (i < NN) {
        float x = c[2 * i], y = c[2 * i + 1];
        float sq = __fadd_rn(__fmul_rn(x, x), __fmul_rn(y, y));
        g_pts[i] = make_float4(x, y, sq, __int_as_float(i));
        unsigned ex = enc_ord(x), ey = enc_ord(y);
        exn = ex; exx = ex; eyn = ey; eyx = ey;
    }
    exn = __reduce_min_sync(FULLM, exn);
    exx = __reduce_max_sync(FULLM, exx);
    eyn = __reduce_min_sync(FULLM, eyn);
    eyx = __reduce_max_sync(FULLM, eyx);
    int w = threadIdx.x >> 5;
    if ((threadIdx.x & 31) == 0) {
        red[0][w] = exn; red[1][w] = exx; red[2][w] = eyn; red[3][w] = eyx;
    }
    __syncthreads();
    if (threadIdx.x < 4) {
        unsigned v = red[threadIdx.x][0];
        bool ismin = (threadIdx.x & 1) == 0;
#pragma unroll
        for (int k = 1; k < 8; k++)
            v = ismin ? min(v, red[threadIdx.x][k]) : max(v, red[threadIdx.x][k]);
        if (ismin) atomicMin(&g_bbox[threadIdx.x], v);
        else       atomicMax(&g_bbox[threadIdx.x], v);
    }
}

// ---------------- K2: bin fill -----------------------------------------------
__global__ void fill_kernel() {
    int i = blockIdx.x * 256 + threadIdx.x;
    if (i >= NN) return;
    Grid g = load_grid();
    float4 p = g_pts[i];
    int cell = cell_y(g, p.y) * G + cell_x(g, p.x);
    int slot = atomicAdd(&g_bcnt[cell], 1);
    if (slot < CAP) g_binpts[cell * CAP + slot] = p;
}

// ---------------- K3: x@W1 ---------------------------------------------------
__global__ void mm1_kernel(const float* __restrict__ x,
                           const float* __restrict__ W1) {
    __shared__ float sw[FIN * 64];
    int tid = threadIdx.x;
    for (int i = tid; i < FIN * 64; i += 256) sw[i] = W1[i];
    __syncthreads();
    int n = blockIdx.x * 4 + (tid >> 6);
    int f = tid & 63;
    const float* xr = x + n * FIN;
    float acc = 0.0f;
#pragma unroll
    for (int k = 0; k < FIN; k++) acc = fmaf(xr[k], sw[k * 64 + f], acc);
    g_bufA[n * 64 + f] = acc;
}

// ---------------- K4 (PROFILED): warp-per-query exact KNN + edges -----------
// One warp = one query. Lanes cooperatively scan the 5x5-cell window
// (>= 2-cell geometric margin). Warp-shared sorted top-16 lives one key
// per lane (lanes 0..15, ascending); candidates passing cmax are inserted
// serially via ballot with a uniform shfl-shift insert (~12 instr).
// Accept iff computed d2_16 + 1e-4 < (2*smin)^2 (outside points are
// >= (2*smin)^2, ulp slack 5e-7) else exact scalar ring-walk fallback.
__global__ void knn_edge_kernel() {
    __shared__ int spref[QPB][26];
    __shared__ int scellb[QPB][25];
    __shared__ unsigned smn, smx;
    const int lane = threadIdx.x & 31;
    const int w = threadIdx.x >> 5;
    if (threadIdx.x == 0) { smn = 0x7F800000u; smx = 0u; }
    __syncthreads();

    const int q = blockIdx.x * QPB + w;
    const Grid g = load_grid();
    const float4 me = g_pts[q];
    const int cx = cell_x(g, me.x);
    const int cy = cell_y(g, me.y);

    // window cell counts (ring order) + warp scan -> shared prefix
    int cnt = 0, cid = 0;
    if (lane < 25) {
        int gx = cx + WDX[lane], gy = cy + WDY[lane];
        if (gx >= 0 && gx < G && gy >= 0 && gy < G) {
            cid = gy * G + gx;
            cnt = min(g_bcnt[cid], CAP);
        }
    }
    int pref = cnt;
#pragma unroll
    for (int off = 1; off < 32; off <<= 1) {
        int v = __shfl_up_sync(FULLM, pref, off);
        if (lane >= off) pref += v;
    }
    if (lane < 25) { spref[w][lane + 1] = pref; scellb[w][lane] = cid * CAP; }
    if (lane == 0) spref[w][0] = 0;
    __syncwarp();
    const int T = __shfl_sync(FULLM, pref, 24);

    unsigned long long lkey = ~0ULL;      // lanes 0..15: sorted top-16
    unsigned long long cmax = ~0ULL;      // current 16th (lane15) key

    const int rounds = (T + 31) >> 5;
    for (int rd = 0; rd < rounds; rd++) {
        int f = rd * 32 + lane;
        unsigned long long mykey = ~0ULL;
        bool pend = false;
        if (f < T) {
            int lo = 0, hi = 24;
#pragma unroll
            for (int it = 0; it < 5; it++) {
                int mid = (lo + hi) >> 1;
                if (spref[w][mid + 1] <= f) lo = mid + 1; else hi = mid;
            }
            float4 pt = g_binpts[scellb[w][lo] + (f - spref[w][lo])];
            int j = __float_as_int(pt.w);
            float dot = __fmaf_rn(me.y, pt.y, __fmul_rn(me.x, pt.x));
            float d2  = __fsub_rn(__fadd_rn(me.z, pt.z), __fmul_rn(2.0f, dot));
            mykey = ((unsigned long long)enc_ord(d2) << 32) | (unsigned)j;
            pend = (j != q) && (mykey < cmax);
        }
        unsigned bal = __ballot_sync(FULLM, pend);
        while (bal) {
            int src = __ffs((int)bal) - 1;
            unsigned long long K = __shfl_sync(FULLM, mykey, src);
            unsigned lt = __ballot_sync(FULLM, lkey < K) & 0xFFFFu;
            int pos = __popc(lt);
            unsigned long long up = __shfl_up_sync(FULLM, lkey, 1);
            lkey = (lane == pos) ? K : ((lane > pos) ? up : lkey);
            cmax = __shfl_sync(FULLM, lkey, 15);
            pend = pend && (lane != src) && (mykey < cmax);
            bal = __ballot_sync(FULLM, pend);
        }
    }

    // exactness certificate: outside-window points have d2 >= (2*smin)^2
    float t16 = dec_ord((unsigned)(cmax >> 32));     // NaN if sentinel
    float bside = __fmul_rn(2.0f, g.smin);
    bool ok = (t16 + 1e-4f < __fmul_rn(bside, bside)); // NaN -> false

    if (ok) {
        unsigned lmn = 0x7F800000u, lmx = 0u;
        if (lane < 16) {
            int j = (int)(lkey & 0xFFFFFFFFULL);
            g_knn[q * KNN + lane] = j;
            float4 nb = g_pts[j];
            float dx = __fsub_rn(me.x, nb.x);
            float dy = __fsub_rn(me.y, nb.y);
            float d  = __fsqrt_rn(__fadd_rn(__fmul_rn(dx, dx),
                                            __fmul_rn(dy, dy)));
            g_d[q * KNN + lane] = d;
            unsigned b = __float_as_uint(d);
            lmn = b; lmx = b;
        }
        lmn = __reduce_min_sync(FULLM, lmn);
        lmx = __reduce_max_sync(FULLM, lmx);
        if (lane == 0) { atomicMin(&smn, lmn); atomicMax(&smx, lmx); }
    } else if (lane == 0) {
        // exact scalar fallback: full expanding ring walk (prob ~0)
        unsigned long long keys[16];
#pragma unroll
        for (int t = 0; t < 16; t++) keys[t] = ~0ULL - (unsigned long long)t;
        unsigned long long cm2 = ~0ULL;
        for (int r = 0; r < G; r++) {
            if (r >= 2) {
                float b = (float)(r - 1) * g.smin;
                float thr = dec_ord((unsigned)(cm2 >> 32));
                if (b * b > thr + 1e-4f) break;
            }
            int y0 = cy - r, y1 = cy + r, x0 = cx - r, x1 = cx + r;
            for (int yy = max(y0, 0); yy <= min(y1, G - 1); yy++) {
                bool erow = (yy == y0) || (yy == y1);
                int xstep = (erow || r == 0) ? 1 : 2 * r;
                for (int xx = x0; xx <= x1; xx += xstep) {
                    if (xx < 0 || xx >= G) continue;
                    int cc = yy * G + xx;
                    int c2 = min(g_bcnt[cc], CAP);
                    const float4* bp = &g_binpts[cc * CAP];
                    for (int p = 0; p < c2; p++) {
                        float4 pt = bp[p];
                        PROCESS(pt, keys, cm2);
                    }
                }
            }
        }
#pragma unroll
        for (int i = 0; i < 15; i++)
#pragma unroll
            for (int t = 0; t < 15 - i; t++)
                if (keys[t] > keys[t + 1]) {
                    unsigned long long tmp = keys[t];
                    keys[t] = keys[t + 1];
                    keys[t + 1] = tmp;
                }
        unsigned lmn = 0x7F800000u, lmx = 0u;
#pragma unroll
        for (int t = 0; t < 16; t++) {
            int j = (int)(keys[t] & 0xFFFFFFFFULL);
            g_knn[q * KNN + t] = j;
            float4 nb = g_pts[j];
            float dx = __fsub_rn(me.x, nb.x);
            float dy = __fsub_rn(me.y, nb.y);
            float d  = __fsqrt_rn(__fadd_rn(__fmul_rn(dx, dx),
                                            __fmul_rn(dy, dy)));
            g_d[q * KNN + t] = d;
            unsigned b = __float_as_uint(d);
            lmn = min(lmn, b);
            lmx = max(lmx, b);
        }
        atomicMin(&smn, lmn);
        atomicMax(&smx, lmx);
    }
    __syncthreads();
    if (threadIdx.x == 0) {
        atomicMin(&g_minmax[0], smn);
        atomicMax(&g_minmax[1], smx);
    }
}

// ---------------- K5: edge weights + deg^{-1/2} (1 thread / edge) -----------
__global__ void deg_kernel() {
    int e = blockIdx.x * 256 + threadIdx.x;     // coalesced over edges
    float mx  = __uint_as_float(g_minmax[1]);
    float rng = __fsub_rn(mx, __uint_as_float(g_minmax[0]));
    float ew  = __fdiv_rn(__fsub_rn(mx, g_d[e]), rng);
    g_ew[e] = ew;
    float s = ew;
#pragma unroll
    for (int off = 8; off > 0; off >>= 1)
        s += __shfl_down_sync(FULLM, s, off, 16);
    if ((threadIdx.x & 15) == 0)
        g_dis[e >> 4] = rsqrtf(__fadd_rn(1.0f, s));   // +1 self-loop
}

// ---------------- K6: agg1 + relu + h1@W2 (row-fused) -----------------------
#define NPB 8
__global__ void agg_mm2_kernel(const float* __restrict__ b1,
                               const float* __restrict__ W2) {
    __shared__ float sw[HID * 64];
    __shared__ float sh1[NPB][64];
    int tid = threadIdx.y * 64 + threadIdx.x;
    for (int i = tid; i < HID * 64; i += 64 * NPB) sw[i] = W2[i];
    int n = blockIdx.x * NPB + threadIdx.y;
    int f = threadIdx.x;
    float disn = g_dis[n];
    float acc = __fmul_rn(__fmul_rn(disn, disn), g_bufA[n * 64 + f]);
#pragma unroll
    for (int k = 0; k < KNN; k++) {
        int s = g_knn[n * KNN + k];
        float coef = __fmul_rn(__fmul_rn(g_dis[s], g_ew[n * KNN + k]), disn);
        acc = fmaf(coef, g_bufA[s * 64 + f], acc);
    }
    sh1[threadIdx.y][f] = fmaxf(__fadd_rn(acc, b1[f]), 0.0f);
    __syncthreads();
    float acc2 = 0.0f;
#pragma unroll
    for (int k = 0; k < HID; k++)
        acc2 = fmaf(sh1[threadIdx.y][k], sw[k * 64 + f], acc2);
    g_bufB[n * 64 + f] = acc2;
}

// ---------------- K7: agg2 + relu + FC head ---------------------------------
__global__ void final_kernel(const float* __restrict__ b2,
                             const float* __restrict__ wfc,
                             const float* __restrict__ bfc,
                             float* __restrict__ y) {
    __shared__ float red[NPB][64];
    int n = blockIdx.x * NPB + threadIdx.y;
    int f = threadIdx.x;
    float disn = g_dis[n];
    float acc = __fmul_rn(__fmul_rn(disn, disn), g_bufB[n * 64 + f]);
#pragma unroll
    for (int k = 0; k < KNN; k++) {
        int s = g_knn[n * KNN + k];
        float coef = __fmul_rn(__fmul_rn(g_dis[s], g_ew[n * KNN + k]), disn);
        acc = fmaf(coef, g_bufB[s * 64 + f], acc);
    }
    float h2 = fmaxf(__fadd_rn(acc, b2[f]), 0.0f);
    red[threadIdx.y][f] = h2 * wfc[f];
    __syncthreads();
#pragma unroll
    for (int off = 32; off > 0; off >>= 1) {
        if (f < off) red[threadIdx.y][f] += red[threadIdx.y][f + off];
        __syncthreads();
    }
    if (f == 0) y[n] = red[threadIdx.y][0] + bfc[0];
}

// ---------------- launch -----------------------------------------------------
extern "C" void kernel_launch(void* const* d_in, const int* in_sizes, int n_in,
                              void* d_out, int out_size) {
    const float* x   = (const float*)d_in[0];
    const float* c   = (const float*)d_in[1];
    const float* W1  = (const float*)d_in[2];
    const float* b1  = (const float*)d_in[3];
    const float* W2  = (const float*)d_in[4];
    const float* b2  = (const float*)d_in[5];
    const float* Wfc = (const float*)d_in[6];
    const float* bfc = (const float*)d_in[7];
    float* y = (float*)d_out;

    prep_kernel<<<63, 256>>>(c);               // launch 0
    fill_kernel<<<63, 256>>>();                // launch 1
    mm1_kernel<<<NN / 4, 256>>>(x, W1);        // launch 2
    knn_edge_kernel<<<NN / QPB, 256>>>();      // launch 3  <- profiled slot
    deg_kernel<<<NN * KNN / 256, 256>>>();
    dim3 blk(64, NPB);
    agg_mm2_kernel<<<NN / NPB, blk>>>(b1, W2);
    final_kernel<<<NN / NPB, blk>>>(b2, Wfc, bfc, y);
}

// round 10
// speedup vs baseline: 1.2835x; 1.0802x over previous
#include <cuda_runtime.h>

#define NN 16000
#define KNN 16
#define FIN 32
#define HID 64
#define G 64
#define NCELL (G * G)
#define CAP 32            // max points per cell (lambda ~3.9)
#define QPB 8             // queries (=warps) per block
#define FULLM 0xFFFFFFFFu

// ---------------- scratch (device globals; no allocation allowed) ----------
__device__ float4 g_pts[NN];              // {x, y, x^2+y^2, id-bits}
__device__ float4 g_binpts[NCELL * CAP];  // packed candidates per cell
__device__ int    g_bcnt[NCELL];          // per-cell fill counts
__device__ int    g_knn[NN * KNN];        // neighbor (src) indices (sorted)
__device__ float  g_d  [NN * KNN];        // edge distances
__device__ float  g_ew [NN * KNN];        // normalized inverted distances
__device__ float  g_dis[NN];              // deg^{-1/2}
__device__ unsigned g_minmax[2];          // [0]=min bits, [1]=max bits (d>=0)
__device__ unsigned g_bbox[4];            // ordered-uint minx,maxx,miny,maxy
__device__ float  g_bufA[NN * HID];       // x@W1
__device__ float  g_bufB[NN * HID];       // h1@W2

// 5x5 window offsets in center-out ring order (tightens cmax early)
__constant__ signed char WDX[25] = {0, -1,0,1,-1,1,-1,0,1,
                                    -2,-1,0,1,2, -2,2, -2,2, -2,2, -2,-1,0,1,2};
__constant__ signed char WDY[25] = {0, -1,-1,-1,0,0,1,1,1,
                                    -2,-2,-2,-2,-2, -1,-1, 0,0, 1,1, 2,2,2,2,2};

// ordered-uint map: monotone with float order (handles negatives)
__device__ __forceinline__ unsigned enc_ord(float f) {
    unsigned b = __float_as_uint(f);
    return (b & 0x80000000u) ? ~b : (b | 0x80000000u);
}
__device__ __forceinline__ float dec_ord(unsigned u) {
    return (u & 0x80000000u) ? __uint_as_float(u & 0x7FFFFFFFu)
                             : __uint_as_float(~u);
}

struct Grid { float minx, miny, invsx, invsy, smin; };
__device__ __forceinline__ Grid load_grid() {
    Grid g;
    g.minx = dec_ord(g_bbox[0]);
    float maxx = dec_ord(g_bbox[1]);
    g.miny = dec_ord(g_bbox[2]);
    float maxy = dec_ord(g_bbox[3]);
    float wx = fmaxf(maxx - g.minx, 1e-20f);
    float wy = fmaxf(maxy - g.miny, 1e-20f);
    g.invsx = (float)G / wx;
    g.invsy = (float)G / wy;
    g.smin  = fminf(wx, wy) / (float)G;
    return g;
}
__device__ __forceinline__ int cell_x(const Grid& g, float x) {
    int c = (int)((x - g.minx) * g.invsx);
    return min(max(c, 0), G - 1);
}
__device__ __forceinline__ int cell_y(const Grid& g, float y) {
    int c = (int)((y - g.miny) * g.invsy);
    return min(max(c, 0), G - 1);
}

// u64 shfl_xor helper
__device__ __forceinline__ unsigned long long shflx64(unsigned long long v,
                                                      int m) {
    unsigned lo = (unsigned)v, hi = (unsigned)(v >> 32);
    lo = __shfl_xor_sync(FULLM, lo, m);
    hi = __shfl_xor_sync(FULLM, hi, m);
    return ((unsigned long long)hi << 32) | lo;
}

// bit-exact d2 + scalar replace-max into KEYS/CMAX (fallback path only)
#define PROCESS(PT, KEYS, CMAX) do {                                       \
    int j = __float_as_int((PT).w);                                        \
    float dot = __fmaf_rn(me.y, (PT).y, __fmul_rn(me.x, (PT).x));          \
    float d2  = __fsub_rn(__fadd_rn(me.z, (PT).z), __fmul_rn(2.0f, dot));  \
    unsigned long long key =                                               \
        ((unsigned long long)enc_ord(d2) << 32) | (unsigned)j;             \
    if (j != q && key < (CMAX)) {                                          \
        unsigned long long nm = 0ULL;                                      \
        _Pragma("unroll")                                                  \
        for (int kk = 0; kk < 16; kk++) {                                  \
            if ((KEYS)[kk] == (CMAX)) (KEYS)[kk] = key;                    \
            nm = max(nm, (KEYS)[kk]);                                      \
        }                                                                  \
        (CMAX) = nm;                                                       \
    }                                                                      \
} while (0)

// ---------------- K1: init + pack + bbox (block-reduced atomics) ------------
__global__ void prep_kernel(const float* __restrict__ c) {
    __shared__ unsigned red[4][8];
    int i = blockIdx.x * 256 + threadIdx.x;
    if (i < NCELL) g_bcnt[i] = 0;
    if (i == 0) { g_minmax[0] = 0x7F800000u; g_minmax[1] = 0u;
                  g_bbox[0] = 0xFFFFFFFFu; g_bbox[1] = 0u;
                  g_bbox[2] = 0xFFFFFFFFu; g_bbox[3] = 0u; }
    unsigned exn = 0xFFFFFFFFu, exx = 0u, eyn = 0xFFFFFFFFu, eyx = 0u;
    if (i < NN) {
        float x = c[2 * i], y = c[2 * i + 1];
        float sq = __fadd_rn(__fmul_rn(x, x), __fmul_rn(y, y));
        g_pts[i] = make_float4(x, y, sq, __int_as_float(i));
        unsigned ex = enc_ord(x), ey = enc_ord(y);
        exn = ex; exx = ex; eyn = ey; eyx = ey;
    }
    exn = __reduce_min_sync(FULLM, exn);
    exx = __reduce_max_sync(FULLM, exx);
    eyn = __reduce_min_sync(FULLM, eyn);
    eyx = __reduce_max_sync(FULLM, eyx);
    int w = threadIdx.x >> 5;
    if ((threadIdx.x & 31) == 0) {
        red[0][w] = exn; red[1][w] = exx; red[2][w] = eyn; red[3][w] = eyx;
    }
    __syncthreads();
    if (threadIdx.x < 4) {
        unsigned v = red[threadIdx.x][0];
        bool ismin = (threadIdx.x & 1) == 0;
#pragma unroll
        for (int k = 1; k < 8; k++)
            v = ismin ? min(v, red[threadIdx.x][k]) : max(v, red[threadIdx.x][k]);
        if (ismin) atomicMin(&g_bbox[threadIdx.x], v);
        else       atomicMax(&g_bbox[threadIdx.x], v);
    }
}

// ---------------- K2: bin fill -----------------------------------------------
__global__ void fill_kernel() {
    int i = blockIdx.x * 256 + threadIdx.x;
    if (i >= NN) return;
    Grid g = load_grid();
    float4 p = g_pts[i];
    int cell = cell_y(g, p.y) * G + cell_x(g, p.x);
    int slot = atomicAdd(&g_bcnt[cell], 1);
    if (slot < CAP) g_binpts[cell * CAP + slot] = p;
}

// ---------------- K3: x@W1 ---------------------------------------------------
__global__ void mm1_kernel(const float* __restrict__ x,
                           const float* __restrict__ W1) {
    __shared__ float sw[FIN * 64];
    int tid = threadIdx.x;
    for (int i = tid; i < FIN * 64; i += 256) sw[i] = W1[i];
    __syncthreads();
    int n = blockIdx.x * 4 + (tid >> 6);
    int f = tid & 63;
    const float* xr = x + n * FIN;
    float acc = 0.0f;
#pragma unroll
    for (int k = 0; k < FIN; k++) acc = fmaf(xr[k], sw[k * 64 + f], acc);
    g_bufA[n * 64 + f] = acc;
}

// ---------------- K4 (PROFILED): warp-per-query exact KNN + edges -----------
// One warp = one query; lanes scan the 5x5 window cooperatively.
// Round 0: 32 keys -> 32-wide bitonic sort across lanes (uniform, ~15
// stages) -> lanes 0..15 hold exact sorted min-16, cmax = lane15.
// Rounds 1+: serial ballot insert (few pending, cmax already tight).
// Accept iff d2_16 + 1e-4 < (2*smin)^2 else exact scalar ring fallback.
__global__ void knn_edge_kernel() {
    __shared__ int spref[QPB][26];
    __shared__ int scellb[QPB][25];
    __shared__ unsigned smn, smx;
    const int lane = threadIdx.x & 31;
    const int w = threadIdx.x >> 5;
    if (threadIdx.x == 0) { smn = 0x7F800000u; smx = 0u; }
    __syncthreads();

    const int q = blockIdx.x * QPB + w;
    const Grid g = load_grid();
    const float4 me = g_pts[q];
    const int cx = cell_x(g, me.x);
    const int cy = cell_y(g, me.y);

    // window cell counts (ring order) + warp scan -> shared prefix
    int cnt = 0, cid = 0;
    if (lane < 25) {
        int gx = cx + WDX[lane], gy = cy + WDY[lane];
        if (gx >= 0 && gx < G && gy >= 0 && gy < G) {
            cid = gy * G + gx;
            cnt = min(g_bcnt[cid], CAP);
        }
    }
    int pref = cnt;
#pragma unroll
    for (int off = 1; off < 32; off <<= 1) {
        int v = __shfl_up_sync(FULLM, pref, off);
        if (lane >= off) pref += v;
    }
    if (lane < 25) { spref[w][lane + 1] = pref; scellb[w][lane] = cid * CAP; }
    if (lane == 0) spref[w][0] = 0;
    __syncwarp();
    const int T = __shfl_sync(FULLM, pref, 24);

    unsigned long long lkey;              // lanes 0..15: sorted top-16
    unsigned long long cmax;              // current 16th (lane15) key

    // ---- round 0: bitonic-sort the first 32 candidate keys ----
    {
        unsigned long long mykey = ~0ULL;
        if (lane < T) {
            int lo = 0, hi = 24;
#pragma unroll
            for (int it = 0; it < 5; it++) {
                int mid = (lo + hi) >> 1;
                if (spref[w][mid + 1] <= lane) lo = mid + 1; else hi = mid;
            }
            float4 pt = g_binpts[scellb[w][lo] + (lane - spref[w][lo])];
            int j = __float_as_int(pt.w);
            float dot = __fmaf_rn(me.y, pt.y, __fmul_rn(me.x, pt.x));
            float d2  = __fsub_rn(__fadd_rn(me.z, pt.z), __fmul_rn(2.0f, dot));
            if (j != q)
                mykey = ((unsigned long long)enc_ord(d2) << 32) | (unsigned)j;
        }
#pragma unroll
        for (int k = 2; k <= 32; k <<= 1) {
#pragma unroll
            for (int jj = k >> 1; jj > 0; jj >>= 1) {
                unsigned long long other = shflx64(mykey, jj);
                bool up = ((lane & k) == 0);
                bool lower = ((lane & jj) == 0);
                bool tmin = (lower == up);
                mykey = tmin ? min(mykey, other) : max(mykey, other);
            }
        }
        lkey = mykey;                         // ascending by lane
        cmax = __shfl_sync(FULLM, lkey, 15);
    }

    // ---- rounds 1+: ballot insert with tight cmax ----
    const int rounds = (T + 31) >> 5;
    for (int rd = 1; rd < rounds; rd++) {
        int f = rd * 32 + lane;
        unsigned long long mykey = ~0ULL;
        bool pend = false;
        if (f < T) {
            int lo = 0, hi = 24;
#pragma unroll
            for (int it = 0; it < 5; it++) {
                int mid = (lo + hi) >> 1;
                if (spref[w][mid + 1] <= f) lo = mid + 1; else hi = mid;
            }
            float4 pt = g_binpts[scellb[w][lo] + (f - spref[w][lo])];
            int j = __float_as_int(pt.w);
            float dot = __fmaf_rn(me.y, pt.y, __fmul_rn(me.x, pt.x));
            float d2  = __fsub_rn(__fadd_rn(me.z, pt.z), __fmul_rn(2.0f, dot));
            mykey = ((unsigned long long)enc_ord(d2) << 32) | (unsigned)j;
            pend = (j != q) && (mykey < cmax);
        }
        unsigned bal = __ballot_sync(FULLM, pend);
        while (bal) {
            int src = __ffs((int)bal) - 1;
            unsigned long long K = __shfl_sync(FULLM, mykey, src);
            unsigned lt = __ballot_sync(FULLM, lkey < K) & 0xFFFFu;
            int pos = __popc(lt);
            unsigned long long up = __shfl_up_sync(FULLM, lkey, 1);
            lkey = (lane == pos) ? K : ((lane > pos) ? up : lkey);
            cmax = __shfl_sync(FULLM, lkey, 15);
            pend = pend && (lane != src) && (mykey < cmax);
            bal = __ballot_sync(FULLM, pend);
        }
    }

    // exactness certificate: outside-window points have d2 >= (2*smin)^2
    float t16 = dec_ord((unsigned)(cmax >> 32));     // NaN if sentinel
    float bside = __fmul_rn(2.0f, g.smin);
    bool ok = (t16 + 1e-4f < __fmul_rn(bside, bside)); // NaN -> false

    if (ok) {
        unsigned lmn = 0x7F800000u, lmx = 0u;
        if (lane < 16) {
            int j = (int)(lkey & 0xFFFFFFFFULL);
            g_knn[q * KNN + lane] = j;
            float4 nb = g_pts[j];
            float dx = __fsub_rn(me.x, nb.x);
            float dy = __fsub_rn(me.y, nb.y);
            float d  = __fsqrt_rn(__fadd_rn(__fmul_rn(dx, dx),
                                            __fmul_rn(dy, dy)));
            g_d[q * KNN + lane] = d;
            unsigned b = __float_as_uint(d);
            lmn = b; lmx = b;
        }
        lmn = __reduce_min_sync(FULLM, lmn);
        lmx = __reduce_max_sync(FULLM, lmx);
        if (lane == 0) { atomicMin(&smn, lmn); atomicMax(&smx, lmx); }
    } else if (lane == 0) {
        // exact scalar fallback: full expanding ring walk (prob ~0)
        unsigned long long keys[16];
#pragma unroll
        for (int t = 0; t < 16; t++) keys[t] = ~0ULL - (unsigned long long)t;
        unsigned long long cm2 = ~0ULL;
        for (int r = 0; r < G; r++) {
            if (r >= 2) {
                float b = (float)(r - 1) * g.smin;
                float thr = dec_ord((unsigned)(cm2 >> 32));
                if (b * b > thr + 1e-4f) break;
            }
            int y0 = cy - r, y1 = cy + r, x0 = cx - r, x1 = cx + r;
            for (int yy = max(y0, 0); yy <= min(y1, G - 1); yy++) {
                bool erow = (yy == y0) || (yy == y1);
                int xstep = (erow || r == 0) ? 1 : 2 * r;
                for (int xx = x0; xx <= x1; xx += xstep) {
                    if (xx < 0 || xx >= G) continue;
                    int cc = yy * G + xx;
                    int c2 = min(g_bcnt[cc], CAP);
                    const float4* bp = &g_binpts[cc * CAP];
                    for (int p = 0; p < c2; p++) {
                        float4 pt = bp[p];
                        PROCESS(pt, keys, cm2);
                    }
                }
            }
        }
#pragma unroll
        for (int i = 0; i < 15; i++)
#pragma unroll
            for (int t = 0; t < 15 - i; t++)
                if (keys[t] > keys[t + 1]) {
                    unsigned long long tmp = keys[t];
                    keys[t] = keys[t + 1];
                    keys[t + 1] = tmp;
                }
        unsigned lmn = 0x7F800000u, lmx = 0u;
#pragma unroll
        for (int t = 0; t < 16; t++) {
            int j = (int)(keys[t] & 0xFFFFFFFFULL);
            g_knn[q * KNN + t] = j;
            float4 nb = g_pts[j];
            float dx = __fsub_rn(me.x, nb.x);
            float dy = __fsub_rn(me.y, nb.y);
            float d  = __fsqrt_rn(__fadd_rn(__fmul_rn(dx, dx),
                                            __fmul_rn(dy, dy)));
            g_d[q * KNN + t] = d;
            unsigned b = __float_as_uint(d);
            lmn = min(lmn, b);
            lmx = max(lmx, b);
        }
        atomicMin(&smn, lmn);
        atomicMax(&smx, lmx);
    }
    __syncthreads();
    if (threadIdx.x == 0) {
        atomicMin(&g_minmax[0], smn);
        atomicMax(&g_minmax[1], smx);
    }
}

// ---------------- K5: edge weights + deg^{-1/2} (1 thread / edge) -----------
__global__ void deg_kernel() {
    int e = blockIdx.x * 256 + threadIdx.x;     // coalesced over edges
    float mx  = __uint_as_float(g_minmax[1]);
    float rng = __fsub_rn(mx, __uint_as_float(g_minmax[0]));
    float ew  = __fdiv_rn(__fsub_rn(mx, g_d[e]), rng);
    g_ew[e] = ew;
    float s = ew;
#pragma unroll
    for (int off = 8; off > 0; off >>= 1)
        s += __shfl_down_sync(FULLM, s, off, 16);
    if ((threadIdx.x & 15) == 0)
        g_dis[e >> 4] = rsqrtf(__fadd_rn(1.0f, s));   // +1 self-loop
}

// ---------------- K6: agg1 + relu + h1@W2 (row-fused) -----------------------
#define NPB 8
__global__ void agg_mm2_kernel(const float* __restrict__ b1,
                               const float* __restrict__ W2) {
    __shared__ float sw[HID * 64];
    __shared__ float sh1[NPB][64];
    int tid = threadIdx.y * 64 + threadIdx.x;
    for (int i = tid; i < HID * 64; i += 64 * NPB) sw[i] = W2[i];
    int n = blockIdx.x * NPB + threadIdx.y;
    int f = threadIdx.x;
    float disn = g_dis[n];
    float acc = __fmul_rn(__fmul_rn(disn, disn), g_bufA[n * 64 + f]);
#pragma unroll
    for (int k = 0; k < KNN; k++) {
        int s = g_knn[n * KNN + k];
        float coef = __fmul_rn(__fmul_rn(g_dis[s], g_ew[n * KNN + k]), disn);
        acc = fmaf(coef, g_bufA[s * 64 + f], acc);
    }
    sh1[threadIdx.y][f] = fmaxf(__fadd_rn(acc, b1[f]), 0.0f);
    __syncthreads();
    float acc2 = 0.0f;
#pragma unroll
    for (int k = 0; k < HID; k++)
        acc2 = fmaf(sh1[threadIdx.y][k], sw[k * 64 + f], acc2);
    g_bufB[n * 64 + f] = acc2;
}

// ---------------- K7: agg2 + relu + FC head ---------------------------------
__global__ void final_kernel(const float* __restrict__ b2,
                             const float* __restrict__ wfc,
                             const float* __restrict__ bfc,
                             float* __restrict__ y) {
    __shared__ float red[NPB][64];
    int n = blockIdx.x * NPB + threadIdx.y;
    int f = threadIdx.x;
    float disn = g_dis[n];
    float acc = __fmul_rn(__fmul_rn(disn, disn), g_bufB[n * 64 + f]);
#pragma unroll
    for (int k = 0; k < KNN; k++) {
        int s = g_knn[n * KNN + k];
        float coef = __fmul_rn(__fmul_rn(g_dis[s], g_ew[n * KNN + k]), disn);
        acc = fmaf(coef, g_bufB[s * 64 + f], acc);
    }
    float h2 = fmaxf(__fadd_rn(acc, b2[f]), 0.0f);
    red[threadIdx.y][f] = h2 * wfc[f];
    __syncthreads();
#pragma unroll
    for (int off = 32; off > 0; off >>= 1) {
        if (f < off) red[threadIdx.y][f] += red[threadIdx.y][f + off];
        __syncthreads();
    }
    if (f == 0) y[n] = red[threadIdx.y][0] + bfc[0];
}

// ---------------- launch -----------------------------------------------------
extern "C" void kernel_launch(void* const* d_in, const int* in_sizes, int n_in,
                              void* d_out, int out_size) {
    const float* x   = (const float*)d_in[0];
    const float* c   = (const float*)d_in[1];
    const float* W1  = (const float*)d_in[2];
    const float* b1  = (const float*)d_in[3];
    const float* W2  = (const float*)d_in[4];
    const float* b2  = (const float*)d_in[5];
    const float* Wfc = (const float*)d_in[6];
    const float* bfc = (const float*)d_in[7];
    float* y = (float*)d_out;

    prep_kernel<<<63, 256>>>(c);               // launch 0
    fill_kernel<<<63, 256>>>();                // launch 1
    mm1_kernel<<<NN / 4, 256>>>(x, W1);        // launch 2
    knn_edge_kernel<<<NN / QPB, 256>>>();      // launch 3  <- profiled slot
    deg_kernel<<<NN * KNN / 256, 256>>>();
    dim3 blk(64, NPB);
    agg_mm2_kernel<<<NN / NPB, blk>>>(b1, W2);
    final_kernel<<<NN / NPB, blk>>>(b2, Wfc, bfc, y);
}